// round 17
// baseline (speedup 1.0000x reference)
#include <cuda_runtime.h>
#include <cstdint>

// SCM_19061064860184 — R17: 2-tick fused bodies on the R16 frame.
// CLC=4 x 128 threads; warp owns 64 positions + 32-halo/side (4 slots/thread).
// Each body advances TWO ticks: one +/-4 shuffle round feeds an extended
// (-2..+5) tick-t compute, which feeds tick t+1 on own slots. Exchange+flush
// every 8 pairs (16 ticks); validity decays 4/side/pair -> halo 32 exact.

#define NN 1024
#define TT 1024
#define NTH 128
#define CLC 4
#define OWNC 256
#define EXW2 320
#define SW 258            // stage stride: %32==2 -> conflict-free flush banks
#define FULLM 0xffffffffu

struct alignas(16) Smem {
    float sEx[2][EXW2];
    float uEx[2][EXW2];
    float stage[16][SW];
};

__device__ __align__(16) float g_scr[8 * NN * TT];
__device__ __align__(16) float g_R[8 * NN * TT + 8 * NN];   // +8 pad rows

__device__ __forceinline__ uint64_t pk2(float lo, float hi) {
    uint64_t r; asm("mov.b64 %0, {%1, %2};" : "=l"(r) : "f"(lo), "f"(hi)); return r;
}
__device__ __forceinline__ void upk2(uint64_t v, float& lo, float& hi) {
    asm("mov.b64 {%0, %1}, %2;" : "=f"(lo), "=f"(hi) : "l"(v));
}
__device__ __forceinline__ uint64_t fma2(uint64_t a, uint64_t b, uint64_t c) {
    uint64_t d; asm("fma.rn.f32x2 %0, %1, %2, %3;" : "=l"(d) : "l"(a), "l"(b), "l"(c)); return d;
}
__device__ __forceinline__ uint64_t add2(uint64_t a, uint64_t b) {
    uint64_t d; asm("add.rn.f32x2 %0, %1, %2;" : "=l"(d) : "l"(a), "l"(b)); return d;
}

__device__ __forceinline__ void conv4acc(float o[4],
    float L2, float L1, float v0, float v1, float v2, float v3, float R0, float R1,
    const float tp[5])
{
    o[0] = fmaf(tp[0], L2, o[0]); o[0] = fmaf(tp[1], L1, o[0]); o[0] = fmaf(tp[2], v0, o[0]);
    o[0] = fmaf(tp[3], v1, o[0]); o[0] = fmaf(tp[4], v2, o[0]);
    o[1] = fmaf(tp[0], L1, o[1]); o[1] = fmaf(tp[1], v0, o[1]); o[1] = fmaf(tp[2], v1, o[1]);
    o[1] = fmaf(tp[3], v2, o[1]); o[1] = fmaf(tp[4], v3, o[1]);
    o[2] = fmaf(tp[0], v0, o[2]); o[2] = fmaf(tp[1], v1, o[2]); o[2] = fmaf(tp[2], v2, o[2]);
    o[2] = fmaf(tp[3], v3, o[2]); o[2] = fmaf(tp[4], R0, o[2]);
    o[3] = fmaf(tp[0], v1, o[3]); o[3] = fmaf(tp[1], v2, o[3]); o[3] = fmaf(tp[2], v3, o[3]);
    o[3] = fmaf(tp[3], R0, o[3]); o[3] = fmaf(tp[4], R1, o[3]);
}

#define HALO4(v0, v1, v2, v3, L2, L1, R0, R1) do { \
    L1 = __shfl_up_sync(FULLM, v3, 1);             \
    L2 = __shfl_up_sync(FULLM, v2, 1);             \
    R0 = __shfl_down_sync(FULLM, v0, 1);           \
    R1 = __shfl_down_sync(FULLM, v1, 1);           \
} while (0)

#define CLUSTER_ARRIVE() asm volatile("barrier.cluster.arrive.aligned;" ::: "memory")
#define CLUSTER_WAIT()   asm volatile("barrier.cluster.wait.aligned;"   ::: "memory")

__device__ __forceinline__ void dsm_store2(const float* lptr, int trank, float a, float b)
{
    uint32_t la = (uint32_t)__cvta_generic_to_shared(lptr);
    uint32_t ra;
    asm volatile("mapa.shared::cluster.u32 %0, %1, %2;" : "=r"(ra) : "r"(la), "r"(trank));
    asm volatile("st.shared::cluster.v2.f32 [%0], {%1, %2};"
                 :: "r"(ra), "f"(a), "f"(b) : "memory");
}

__device__ __forceinline__ void stage_store4(float* p, float a, float b, float c, float d)
{
    *reinterpret_cast<float2*>(p)     = make_float2(a, b);
    *reinterpret_cast<float2*>(p + 2) = make_float2(c, d);
}

// warp-private flush of 16 u-rows (i0..i0+15, i0 % 16 == 0)
__device__ __forceinline__ void flushw(const float (*stg)[SW], float* __restrict__ O,
                                       int i0, int w, int lane, int rank)
{
    const int q = lane & 3;
    const int r = lane >> 2;
    const int cb = NN - 4 - i0 - 4 * q;
    #pragma unroll
    for (int k = 0; k < 8; ++k) {
        const int oi = r + 8 * k;
        const int sa = w * 64 + oi;
        float4 v;
        v.x = stg[(i0 + 4 * q + 3) & 15][sa];
        v.y = stg[(i0 + 4 * q + 2) & 15][sa];
        v.z = stg[(i0 + 4 * q + 1) & 15][sa];
        v.w = stg[(i0 + 4 * q + 0) & 15][sa];
        *reinterpret_cast<float4*>(O + (size_t)(rank * OWNC + w * 64 + oi) * NN + cb) = v;
    }
}

template <int COLTAPS, int PHASE>
__global__ void __launch_bounds__(NTH, 1) __cluster_dims__(CLC, 1, 1)
scan_kernel(float* __restrict__ OUTparam,
            const float* __restrict__ preBw, const float* __restrict__ preBb,
            const float* __restrict__ cAw,
            const float* __restrict__ cBw, const float* __restrict__ cBb)
{
    extern __shared__ char raw[];
    Smem* sm = reinterpret_cast<Smem*>(raw);
    const int rank  = blockIdx.x & (CLC - 1);
    const int batch = blockIdx.x >> 2;
    const float* RIN = g_R + (size_t)batch * NN * TT;
    float* O = (PHASE == 0 ? g_scr : OUTparam) + (size_t)batch * NN * TT;

    const int tid = threadIdx.x, w = tid >> 5, lane = tid & 31;
#define TI(k) (COLTAPS ? (5 * (k) + 2) : (10 + (k)))
    float aS[5], bS[5], bX[5], pB[5];
    uint64_t aSp[5], bSp[5], bXp[5];
    #pragma unroll
    for (int k = 0; k < 5; ++k) {
        aS[k] = cAw[TI(k)];
        bS[k] = cBw[TI(k)];
        bX[k] = cBw[25 + TI(k)];
        pB[k] = preBw[TI(k)];
        aSp[k] = pk2(aS[k], aS[k]);
        bSp[k] = pk2(bS[k], bS[k]);
        bXp[k] = pk2(bX[k], bX[k]);
    }
    const float bB = cBb[0], pBb = preBb[0];
    const uint64_t bBp = pk2(bB, bB);
    const uint64_t Z64 = pk2(0.f, 0.f);
#undef TI

    const int wg = rank * 4 + w;
    const int g0 = wg * 64 - 32 + 4 * lane;
    bool inD[4], inDx[8];
    #pragma unroll
    for (int j = 0; j < 4; ++j) inD[j] = (g0 + j >= 0) && (g0 + j < NN);
    #pragma unroll
    for (int j = 0; j < 8; ++j) inDx[j] = (g0 - 2 + j >= 0) && (g0 - 2 + j < NN);
    const bool own = (lane >= 8 && lane < 24);
    const bool edgeW = (wg == 0) || (wg == CLC * 4 - 1);
    const int exIdx = w * 64 + 4 * lane;
    const int stIdx = exIdx - 32;
    const bool pubL = (rank > 0) && (w == 0) && (lane >= 8 && lane < 16);
    const bool pubR = (rank < CLC - 1) && (w == 3) && (lane >= 16 && lane < 24);
    const int gr  = g0 < 0 ? 0 : (g0 > NN - 4 ? NN - 4 : g0);
    const int gmc = g0 - 4 < 0 ? 0 : (g0 - 4 > NN - 4 ? NN - 4 : g0 - 4);
    const int gpc = g0 + 4 < 0 ? 0 : (g0 + 4 > NN - 4 ? NN - 4 : g0 + 4);
    const float (*stg)[SW] = sm->stage;

    {
        float* p0 = &sm->sEx[0][0];
        float* p1 = &sm->uEx[0][0];
        for (int i = tid; i < 2 * EXW2; i += NTH) { p0[i] = 0.f; p1[i] = 0.f; }
    }
    CLUSTER_ARRIVE();
    CLUSTER_WAIT();

    auto rowO = [&](int t) { return reinterpret_cast<const float4*>(RIN + (size_t)t * NN + gr); };
    auto rowM = [&](int t) { return reinterpret_cast<const float4*>(RIN + (size_t)t * NN + gmc); };
    auto rowP = [&](int t) { return reinterpret_cast<const float4*>(RIN + (size_t)t * NN + gpc); };

    float s0, s1, s2, s3, u0, u1, u2, u3;

    // ---- t = 0 ----
    {
        float4 r = *rowO(0);
        s0 = inD[0] ? r.x : 0.f;
        s1 = inD[1] ? r.y : 0.f;
        s2 = inD[2] ? r.z : 0.f;
        s3 = inD[3] ? r.w : 0.f;
    }
    // ---- t = 1 (scalar): s_1, u_0 ----
    {
        float4 r = *rowO(1);
        float L2, L1, R0, R1;
        HALO4(s0, s1, s2, s3, L2, L1, R0, R1);
        float a[4] = {r.x, r.y, r.z, r.w};
        conv4acc(a, L2, L1, s0, s1, s2, s3, R0, R1, aS);
        float c[4] = {pBb, pBb, pBb, pBb};
        conv4acc(c, L2, L1, s0, s1, s2, s3, R0, R1, pB);
        if (edgeW) {
            #pragma unroll
            for (int j = 0; j < 4; ++j) if (!inD[j]) { a[j] = 0.f; c[j] = 0.f; }
        }
        s0 = a[0]; s1 = a[1]; s2 = a[2]; s3 = a[3];
        u0 = c[0]; u1 = c[1]; u2 = c[2]; u3 = c[3];
        if (own) stage_store4(&sm->stage[0][stIdx], u0, u1, u2, u3);
    }
    // ---- t = 2 (scalar): s_2, u_1 ----
    {
        float4 r = *rowO(2);
        float sL2, sL1, sR0, sR1, uL2, uL1, uR0, uR1;
        HALO4(s0, s1, s2, s3, sL2, sL1, sR0, sR1);
        HALO4(u0, u1, u2, u3, uL2, uL1, uR0, uR1);
        float a[4] = {r.x, r.y, r.z, r.w};
        conv4acc(a, sL2, sL1, s0, s1, s2, s3, sR0, sR1, aS);
        float cu[4] = {bB, bB, bB, bB};
        conv4acc(cu, uL2, uL1, u0, u1, u2, u3, uR0, uR1, bS);
        float cs[4] = {0.f, 0.f, 0.f, 0.f};
        conv4acc(cs, sL2, sL1, s0, s1, s2, s3, sR0, sR1, bX);
        float c[4] = {cu[0] + cs[0], cu[1] + cs[1], cu[2] + cs[2], cu[3] + cs[3]};
        if (edgeW) {
            #pragma unroll
            for (int j = 0; j < 4; ++j) if (!inD[j]) { a[j] = 0.f; c[j] = 0.f; }
        }
        s0 = a[0]; s1 = a[1]; s2 = a[2]; s3 = a[3];
        u0 = c[0]; u1 = c[1]; u2 = c[2]; u3 = c[3];
        if (own) stage_store4(&sm->stage[1][stIdx], u0, u1, u2, u3);
    }

    int eb = 0;

    // pair body: ticks (t, t+1), t odd. In: (s_{t-1}, u_{t-2}); out: (s_{t+1}, u_t).
    auto pair = [&](int t, float4& rm, float4& r0, float4& rp, float4& rb,
                    const float4* lm, const float4* l0, const float4* lp, const float4* lb) {
        // +/-4 halo of s_{t-1} and u_{t-2}
        float sm4 = __shfl_up_sync(FULLM, s0, 1), sm3 = __shfl_up_sync(FULLM, s1, 1);
        float sm2 = __shfl_up_sync(FULLM, s2, 1), sm1 = __shfl_up_sync(FULLM, s3, 1);
        float sp4 = __shfl_down_sync(FULLM, s0, 1), sp5 = __shfl_down_sync(FULLM, s1, 1);
        float sp6 = __shfl_down_sync(FULLM, s2, 1), sp7 = __shfl_down_sync(FULLM, s3, 1);
        float um4 = __shfl_up_sync(FULLM, u0, 1), um3 = __shfl_up_sync(FULLM, u1, 1);
        float um2 = __shfl_up_sync(FULLM, u2, 1), um1 = __shfl_up_sync(FULLM, u3, 1);
        float up4 = __shfl_down_sync(FULLM, u0, 1), up5 = __shfl_down_sync(FULLM, u1, 1);
        float up6 = __shfl_down_sync(FULLM, u2, 1), up7 = __shfl_down_sync(FULLM, u3, 1);

        // shifted packs m = -4..6 (Ps[m] = (sE[m], sE[m+1]))
        uint64_t Ps[11], Pu[11];
        {
            float sE[12] = {sm4, sm3, sm2, sm1, s0, s1, s2, s3, sp4, sp5, sp6, sp7};
            float uE[12] = {um4, um3, um2, um1, u0, u1, u2, u3, up4, up5, up6, up7};
            #pragma unroll
            for (int m = 0; m < 11; ++m) { Ps[m] = pk2(sE[m], sE[m + 1]); Pu[m] = pk2(uE[m], uE[m + 1]); }
        }

        // tick t on extended slots -2..5 (pipes: (-2,-1),(0,1),(2,3),(4,5))
        uint64_t SX[4], UX[4];
        {
            uint64_t a0 = pk2(rm.z, rm.w), a1 = pk2(r0.x, r0.y),
                     a2 = pk2(r0.z, r0.w), a3 = pk2(rp.x, rp.y);
            uint64_t cu0 = bBp, cu1 = bBp, cu2 = bBp, cu3 = bBp;
            uint64_t cs0 = Z64, cs1 = Z64, cs2 = Z64, cs3 = Z64;
            #pragma unroll
            for (int k = 0; k < 5; ++k) {
                a0 = fma2(aSp[k], Ps[k],     a0);
                a1 = fma2(aSp[k], Ps[k + 2], a1);
                a2 = fma2(aSp[k], Ps[k + 4], a2);
                a3 = fma2(aSp[k], Ps[k + 6], a3);
                cu0 = fma2(bSp[k], Pu[k],     cu0);
                cu1 = fma2(bSp[k], Pu[k + 2], cu1);
                cu2 = fma2(bSp[k], Pu[k + 4], cu2);
                cu3 = fma2(bSp[k], Pu[k + 6], cu3);
                cs0 = fma2(bXp[k], Ps[k],     cs0);
                cs1 = fma2(bXp[k], Ps[k + 2], cs1);
                cs2 = fma2(bXp[k], Ps[k + 4], cs2);
                cs3 = fma2(bXp[k], Ps[k + 6], cs3);
            }
            SX[0] = a0; SX[1] = a1; SX[2] = a2; SX[3] = a3;
            UX[0] = add2(cu0, cs0); UX[1] = add2(cu1, cs1);
            UX[2] = add2(cu2, cs2); UX[3] = add2(cu3, cs3);
        }
        float sx[8], ux[8];
        upk2(SX[0], sx[0], sx[1]); upk2(SX[1], sx[2], sx[3]);
        upk2(SX[2], sx[4], sx[5]); upk2(SX[3], sx[6], sx[7]);
        upk2(UX[0], ux[0], ux[1]); upk2(UX[1], ux[2], ux[3]);
        upk2(UX[2], ux[4], ux[5]); upk2(UX[3], ux[6], ux[7]);
        if (edgeW) {
            #pragma unroll
            for (int j = 0; j < 8; ++j) if (!inDx[j]) { sx[j] = 0.f; ux[j] = 0.f; }
        }

        // tick t+1 on own slots
        uint64_t Qs[7], Qu[7];
        #pragma unroll
        for (int m = 0; m < 7; ++m) { Qs[m] = pk2(sx[m], sx[m + 1]); Qu[m] = pk2(ux[m], ux[m + 1]); }
        uint64_t A0 = pk2(rb.x, rb.y), A1 = pk2(rb.z, rb.w);
        uint64_t CU0 = bBp, CU1 = bBp, CS0 = Z64, CS1 = Z64;
        #pragma unroll
        for (int k = 0; k < 5; ++k) {
            A0 = fma2(aSp[k], Qs[k], A0);
            A1 = fma2(aSp[k], Qs[k + 2], A1);
            CU0 = fma2(bSp[k], Qu[k], CU0);
            CU1 = fma2(bSp[k], Qu[k + 2], CU1);
            CS0 = fma2(bXp[k], Qs[k], CS0);
            CS1 = fma2(bXp[k], Qs[k + 2], CS1);
        }
        const uint64_t C0 = add2(CU0, CS0), C1 = add2(CU1, CS1);
        float a0, a1, a2, a3, c0, c1, c2, c3;
        upk2(A0, a0, a1); upk2(A1, a2, a3);
        upk2(C0, c0, c1); upk2(C1, c2, c3);
        if (edgeW) {
            if (!inD[0]) { a0 = 0.f; c0 = 0.f; }
            if (!inD[1]) { a1 = 0.f; c1 = 0.f; }
            if (!inD[2]) { a2 = 0.f; c2 = 0.f; }
            if (!inD[3]) { a3 = 0.f; c3 = 0.f; }
        }
        if (own) {
            stage_store4(&sm->stage[(t - 1) & 15][stIdx], ux[2], ux[3], ux[4], ux[5]);  // u_{t-1} own
            stage_store4(&sm->stage[t & 15][stIdx], c0, c1, c2, c3);                    // u_t
        }
        s0 = a0; s1 = a1; s2 = a2; s3 = a3;
        u0 = c0; u1 = c1; u2 = c2; u3 = c3;

        rm = *lm; r0 = *l0; rp = *lp; rb = *lb;    // prefetch pair t+4

        if (((t + 1) & 15) == 0) {                 // exchange + flush (every 8 pairs)
            const int buf = eb; eb ^= 1;
            if (own) {
                *reinterpret_cast<float4*>(&sm->sEx[buf][exIdx]) = make_float4(s0, s1, s2, s3);
                *reinterpret_cast<float4*>(&sm->uEx[buf][exIdx]) = make_float4(u0, u1, u2, u3);
                if (pubR) {
                    dsm_store2(&sm->sEx[buf][exIdx - 256], rank + 1, s0, s1);
                    dsm_store2(&sm->sEx[buf][exIdx - 254], rank + 1, s2, s3);
                    dsm_store2(&sm->uEx[buf][exIdx - 256], rank + 1, u0, u1);
                    dsm_store2(&sm->uEx[buf][exIdx - 254], rank + 1, u2, u3);
                }
                if (pubL) {
                    dsm_store2(&sm->sEx[buf][exIdx + 256], rank - 1, s0, s1);
                    dsm_store2(&sm->sEx[buf][exIdx + 258], rank - 1, s2, s3);
                    dsm_store2(&sm->uEx[buf][exIdx + 256], rank - 1, u0, u1);
                    dsm_store2(&sm->uEx[buf][exIdx + 258], rank - 1, u2, u3);
                }
            }
            CLUSTER_ARRIVE();
            __syncwarp();
            flushw(stg, O, t + 1 - 16, w, lane, rank);
            CLUSTER_WAIT();
            if (!own) {
                float4 sv = *reinterpret_cast<const float4*>(&sm->sEx[buf][exIdx]);
                float4 uv = *reinterpret_cast<const float4*>(&sm->uEx[buf][exIdx]);
                s0 = sv.x; s1 = sv.y; s2 = sv.z; s3 = sv.w;
                u0 = uv.x; u1 = uv.y; u2 = uv.z; u3 = uv.w;
            }
        }
    };

    // preload pairs t=3 and t=5
    float4 rmA = *rowM(3), r0A = *rowO(3), rpA = *rowP(3), rbA = *rowO(4);
    float4 rmB = *rowM(5), r0B = *rowO(5), rpB = *rowP(5), rbB = *rowO(6);

    // pairs t = 3,5,...,1021 (510 pairs, 255 iterations)
    #pragma unroll 1
    for (int t = 3; t <= 1021; t += 4) {
        pair(t,     rmA, r0A, rpA, rbA, rowM(t + 4), rowO(t + 4), rowP(t + 4), rowO(t + 5));
        pair(t + 2, rmB, r0B, rpB, rbB, rowM(t + 6), rowO(t + 6), rowP(t + 6), rowO(t + 7));
    }

    // ---- t = 1023 (scalar): s_1023, u_1022 ----
    {
        float4 r = *rowO(1023);
        float sL2, sL1, sR0, sR1, uL2, uL1, uR0, uR1;
        HALO4(s0, s1, s2, s3, sL2, sL1, sR0, sR1);
        HALO4(u0, u1, u2, u3, uL2, uL1, uR0, uR1);
        float a[4] = {r.x, r.y, r.z, r.w};
        conv4acc(a, sL2, sL1, s0, s1, s2, s3, sR0, sR1, aS);
        float cu[4] = {bB, bB, bB, bB};
        conv4acc(cu, uL2, uL1, u0, u1, u2, u3, uR0, uR1, bS);
        float cs[4] = {0.f, 0.f, 0.f, 0.f};
        conv4acc(cs, sL2, sL1, s0, s1, s2, s3, sR0, sR1, bX);
        float c[4] = {cu[0] + cs[0], cu[1] + cs[1], cu[2] + cs[2], cu[3] + cs[3]};
        if (edgeW) {
            #pragma unroll
            for (int j = 0; j < 4; ++j) if (!inD[j]) { a[j] = 0.f; c[j] = 0.f; }
        }
        s0 = a[0]; s1 = a[1]; s2 = a[2]; s3 = a[3];
        u0 = c[0]; u1 = c[1]; u2 = c[2]; u3 = c[3];
        if (own) stage_store4(&sm->stage[14][stIdx], u0, u1, u2, u3);   // u_1022
    }
    // ---- epilogue: u_1023 + final flush ----
    {
        float sL2, sL1, sR0, sR1, uL2, uL1, uR0, uR1;
        HALO4(s0, s1, s2, s3, sL2, sL1, sR0, sR1);
        HALO4(u0, u1, u2, u3, uL2, uL1, uR0, uR1);
        float cu[4] = {bB, bB, bB, bB};
        conv4acc(cu, uL2, uL1, u0, u1, u2, u3, uR0, uR1, bS);
        float cs[4] = {0.f, 0.f, 0.f, 0.f};
        conv4acc(cs, sL2, sL1, s0, s1, s2, s3, sR0, sR1, bX);
        float c[4] = {cu[0] + cs[0], cu[1] + cs[1], cu[2] + cs[2], cu[3] + cs[3]};
        if (edgeW) {
            #pragma unroll
            for (int j = 0; j < 4; ++j) if (!inD[j]) c[j] = 0.f;
        }
        if (own) stage_store4(&sm->stage[15][stIdx], c[0], c[1], c[2], c[3]);  // u_1023
        __syncwarp();
        flushw(stg, O, 1008, w, lane, rank);
    }
}

// R[b][0][p] = pre_b + conv(pre taps, src[b][0]) ; R[b][t][p] = c_b + conv(c x-taps, src[b][t])
template <int COLTAPS, int PHASE>
__global__ void __launch_bounds__(256)
yprep(const float* __restrict__ srcparam,
      const float* __restrict__ pw, const float* __restrict__ pb,
      const float* __restrict__ cw, const float* __restrict__ cbias)
{
    const int r = blockIdx.x & (TT - 1);
    const int b = blockIdx.x >> 10;
    const float* src = (PHASE == 0 ? srcparam : (const float*)g_scr);
    const float* xr = src + ((size_t)b * TT + r) * NN;
    float* yr = g_R + ((size_t)b * TT + r) * NN;
    float tp[5], bias;
    #pragma unroll
    for (int k = 0; k < 5; ++k) {
        const int ti = COLTAPS ? (5 * k + 2) : (10 + k);
        tp[k] = (r == 0) ? pw[ti] : cw[25 + ti];
    }
    bias = (r == 0) ? pb[0] : cbias[0];
    const int p0 = threadIdx.x * 4;
    #pragma unroll
    for (int j = 0; j < 4; ++j) {
        const int p = p0 + j;
        float acc = bias;
        #pragma unroll
        for (int k = 0; k < 5; ++k) {
            const int q = p + k - 2;
            const float v = (q >= 0 && q < NN) ? __ldg(xr + q) : 0.f;
            acc = fmaf(tp[k], v, acc);
        }
        yr[p] = acc;
    }
}

extern "C" void kernel_launch(void* const* d_in, const int* in_sizes, int n_in,
                              void* d_out, int out_size)
{
    (void)in_sizes; (void)n_in; (void)out_size;
    const float* x   = (const float*)d_in[0];
    const float* p1w = (const float*)d_in[1];
    const float* p1b = (const float*)d_in[2];
    const float* p2w = (const float*)d_in[3];
    const float* p2b = (const float*)d_in[4];
    const float* p3w = (const float*)d_in[5];
    const float* p3b = (const float*)d_in[6];
    const float* p4w = (const float*)d_in[7];
    const float* p4b = (const float*)d_in[8];
    const float* c1w = (const float*)d_in[9];
    const float* c1b = (const float*)d_in[10];
    const float* c2w = (const float*)d_in[11];
    const float* c2b = (const float*)d_in[12];
    const float* c3w = (const float*)d_in[13];
    const float* c3b = (const float*)d_in[14];
    const float* c4w = (const float*)d_in[15];
    const float* c4b = (const float*)d_in[16];

    cudaFuncSetAttribute(scan_kernel<0, 0>, cudaFuncAttributeMaxDynamicSharedMemorySize, (int)sizeof(Smem));
    cudaFuncSetAttribute(scan_kernel<1, 1>, cudaFuncAttributeMaxDynamicSharedMemorySize, (int)sizeof(Smem));

    yprep<0, 0><<<8 * TT, 256>>>(x, p1w, p1b, c1w, c1b);
    scan_kernel<0, 0><<<8 * CLC, NTH, sizeof(Smem)>>>(nullptr, p2w, p2b, c1w, c2w, c2b);
    yprep<1, 1><<<8 * TT, 256>>>(nullptr, p3w, p3b, c3w, c3b);
    scan_kernel<1, 1><<<8 * CLC, NTH, sizeof(Smem)>>>((float*)d_out, p4w, p4b, c3w, c4w, c4b);
}